// round 13
// baseline (speedup 1.0000x reference)
#include <cuda_runtime.h>
#include <cuda_fp16.h>
#include <stdint.h>
#include <string.h>

#define K_DIM 2048
#define N_DIM 2048
#define TOPK  1024
#define BM 128
#define BN 128
#define BK 64
#define STAGES 3
#define TILE_BYTES (BM * BK * 2)          // 16 KB per operand tile
#define STAGE_BYTES (2 * TILE_BYTES)      // A + B = 32 KB
#define NITER (K_DIM / BK)                // 32
#define MASK_BLOCKS 2048

// Masked weights, fp16 row-major (device global: allocation-free rule).
// NOTE: no g_A anymore — x is converted inline inside the GEMM.
__device__ __align__(16) __half g_B[(size_t)N_DIM * K_DIM];

// ---------------------------------------------------------------------------
// PTX helpers (baseline sm_80+ features only: valid for compute_103 PTX)
// ---------------------------------------------------------------------------
__device__ __forceinline__ uint32_t smem_u32(const void* p) {
    uint32_t a;
    asm("{ .reg .u64 t; cvta.to.shared.u64 t, %1; cvt.u32.u64 %0, t; }" : "=r"(a) : "l"(p));
    return a;
}
__device__ __forceinline__ void cpa16(uint32_t dst, const void* src) {
    asm volatile("cp.async.cg.shared.global [%0], [%1], 16;" :: "r"(dst), "l"(src) : "memory");
}
__device__ __forceinline__ void cpa_commit() {
    asm volatile("cp.async.commit_group;" ::: "memory");
}
__device__ __forceinline__ void cpa_wait1() {
    asm volatile("cp.async.wait_group 1;" ::: "memory");
}
__device__ __forceinline__ void ldsm_x4(uint32_t (&r)[4], uint32_t addr) {
    asm volatile("ldmatrix.sync.aligned.m8n8.x4.shared.b16 {%0,%1,%2,%3}, [%4];"
                 : "=r"(r[0]), "=r"(r[1]), "=r"(r[2]), "=r"(r[3]) : "r"(addr));
}
__device__ __forceinline__ void mma_fp16(float (&c)[4], const uint32_t (&a)[4],
                                         uint32_t b0, uint32_t b1) {
    asm volatile(
        "mma.sync.aligned.m16n8k16.row.col.f32.f16.f16.f32 "
        "{%0,%1,%2,%3}, {%4,%5,%6,%7}, {%8,%9}, {%0,%1,%2,%3};"
        : "+f"(c[0]), "+f"(c[1]), "+f"(c[2]), "+f"(c[3])
        : "r"(a[0]), "r"(a[1]), "r"(a[2]), "r"(a[3]), "r"(b0), "r"(b1));
}
// Convert 8 fp32 -> 8 fp16 and store 16B to shared.
__device__ __forceinline__ void sts_a8(unsigned char* smem, uint32_t off,
                                       const float4& va, const float4& vb) {
    __half2 h0 = __floats2half2_rn(va.x, va.y);
    __half2 h1 = __floats2half2_rn(va.z, va.w);
    __half2 h2 = __floats2half2_rn(vb.x, vb.y);
    __half2 h3 = __floats2half2_rn(vb.z, vb.w);
    uint4 pk;
    memcpy(&pk.x, &h0, 4); memcpy(&pk.y, &h1, 4);
    memcpy(&pk.z, &h2, 4); memcpy(&pk.w, &h3, 4);
    *(uint4*)(smem + off) = pk;
}

// ---------------------------------------------------------------------------
// Prep kernel: mask ONLY (x conversion is fused into the GEMM).
// Per-row exact top-k radix select -> g_B fp16. One 256-thread block per row.
// ---------------------------------------------------------------------------
__global__ __launch_bounds__(256) void prep_kernel(const float* __restrict__ w) {
    __shared__ unsigned int bits[K_DIM];
    __shared__ unsigned int hA[256];
    __shared__ unsigned int hBuf[256];
    __shared__ unsigned int s_prefix, s_kwant, s_cnt_gt, s_cnt_eq;

    const int tid = threadIdx.x;
    const int row = blockIdx.x;
    const float* wr = w + (size_t)row * K_DIM;

    for (int i = tid; i < K_DIM; i += 256)
        bits[i] = __float_as_uint(wr[i]) & 0x7FFFFFFFu;
    if (tid == 0) { s_cnt_gt = 0; s_cnt_eq = 0; }
    __syncthreads();

    unsigned int prefix = 0, kwant = TOPK;
    #pragma unroll
    for (int pass = 3; pass >= 0; --pass) {
        const int shift = pass * 8;
        hA[tid] = 0;
        __syncthreads();
        if (pass == 3) {
            for (int i = tid; i < K_DIM; i += 256)
                atomicAdd(&hA[(bits[i] >> shift) & 0xFFu], 1u);
        } else {
            const unsigned int hi_mask = 0xFFFFFFFFu << (shift + 8);
            for (int i = tid; i < K_DIM; i += 256) {
                const unsigned int b = bits[i];
                if ((b & hi_mask) == (prefix & hi_mask))
                    atomicAdd(&hA[(b >> shift) & 0xFFu], 1u);
            }
        }
        __syncthreads();

        // Parallel inclusive suffix scan: S(i) = sum_{j>=i} hist[j]
        unsigned int* cur = hA;
        unsigned int* nxt = hBuf;
        unsigned int v = cur[tid];
        #pragma unroll
        for (int step = 1; step < 256; step <<= 1) {
            unsigned int add = (tid + step < 256) ? cur[tid + step] : 0u;
            v += add;
            nxt[tid] = v;
            unsigned int* tmp = cur; cur = nxt; nxt = tmp;
            __syncthreads();
        }
        const unsigned int S_next = (tid == 255) ? 0u : cur[tid + 1];
        if (v >= kwant && S_next < kwant) {
            s_prefix = prefix | ((unsigned int)tid << shift);
            s_kwant  = kwant - S_next;
        }
        __syncthreads();
        prefix = s_prefix;
        kwant  = s_kwant;
        __syncthreads();
    }
    const unsigned int thresh = prefix;

    unsigned int local_gt = 0, local_eq = 0;
    for (int i = tid; i < K_DIM; i += 256) {
        local_gt += (bits[i] > thresh);
        local_eq += (bits[i] == thresh);
    }
    if (local_gt) atomicAdd(&s_cnt_gt, local_gt);
    if (local_eq) atomicAdd(&s_cnt_eq, local_eq);
    __syncthreads();
    const unsigned int need_eq = TOPK - s_cnt_gt;
    const bool keep_all_eq = (s_cnt_eq == need_eq);   // no true fp ties (common)

    for (int i = tid; i < K_DIM; i += 256) {
        const unsigned int b = bits[i];
        float val = 0.0f;
        if (b > thresh) {
            val = wr[i];
        } else if (b == thresh) {
            if (keep_all_eq) {
                val = wr[i];
            } else {
                unsigned int rr = 0;
                for (int j = 0; j < i; ++j) rr += (bits[j] == thresh);
                if (rr < need_eq) val = wr[i];
            }
        }
        g_B[(size_t)row * K_DIM + i] = __float2half_rn(val);
    }
}

// ---------------------------------------------------------------------------
// GEMM: pipelined mma.sync fp16 with INLINE x fp32->fp16 conversion.
// A-path: per-thread LDG.128 of raw x, prefetched 2 stages ahead into regs,
//         converted + STS at iteration end (hidden behind the HMMA block).
// B-path: cp.async 3-stage pipeline as before.
// 128x128 tile/CTA, 256 thr (2x4 warps of 64x32), one barrier per K-iter.
// ---------------------------------------------------------------------------
__global__ void __launch_bounds__(256) gemm_mma(const float* __restrict__ x,
                                                const float* __restrict__ bias,
                                                float* __restrict__ y) {
    extern __shared__ unsigned char dyn_smem[];
    const uint32_t sbase = smem_u32(dyn_smem);

    const int tid  = threadIdx.x;
    const int wid  = tid >> 5;
    const int lane = tid & 31;
    const int m_tile = blockIdx.x >> 4;
    const int n_tile = blockIdx.x & 15;
    const int m0 = m_tile * BM;
    const int n0 = n_tile * BN;

    // Per-thread load mapping: row set {r0+32u}, fixed k-chunk ch, fixed swizzle cs
    const int r0 = tid >> 3;                  // 0..31
    const int ch = tid & 7;                   // 0..7
    const int cs = ch ^ (r0 & 7);             // swizzled chunk column
    const uint32_t aoff0 = (uint32_t)r0 * 128u + (uint32_t)cs * 16u;
    const float* xbase = x + (size_t)(m0 + r0) * K_DIM + ch * 8;

    const int wm = wid >> 2;          // 0..1
    const int wn = wid & 3;           // 0..3
    const int lr = lane & 15;
    const int lc = lane >> 4;
    const int arow0 = wm * 64 + lr;
    const int brow0 = wn * 32 + lr;

    float acc[4][4][4];
    #pragma unroll
    for (int i = 0; i < 4; ++i)
        #pragma unroll
        for (int j = 0; j < 4; ++j)
            #pragma unroll
            for (int r = 0; r < 4; ++r) acc[i][j][r] = 0.0f;

    // -- prologue: fill stages 0,1 --
    #pragma unroll
    for (int s = 0; s < 2; ++s) {
        const int kc = s * BK;
        unsigned char* sA = dyn_smem + s * STAGE_BYTES;
        const uint32_t sB = sbase + s * STAGE_BYTES + TILE_BYTES;
        #pragma unroll
        for (int u = 0; u < 4; ++u) {
            const float* src = xbase + (size_t)u * 32 * K_DIM + kc;
            const float4 va = *(const float4*)src;
            const float4 vb = *(const float4*)(src + 4);
            sts_a8(sA, aoff0 + u * 4096u, va, vb);
            cpa16(sB + aoff0 + u * 4096u,
                  g_B + (size_t)(n0 + r0 + u * 32) * K_DIM + kc + ch * 8);
        }
        cpa_commit();
    }

    for (int it = 0; it < NITER; ++it) {
        const int st = it % STAGES;
        cpa_wait1();          // B stage `it` landed (1 newer group pending)
        __syncthreads();      // A STS + B visible; stage (it+2)%3 consumed at it-1

        const bool pf = (it + 2) < NITER;
        const int pst = (it + 2) % STAGES;
        const int pkc = (it + 2) * BK;
        float4 fb[8];
        if (pf) {
            // issue A LDGs early (latency hidden behind the HMMA block below)
            #pragma unroll
            for (int u = 0; u < 4; ++u) {
                const float* src = xbase + (size_t)u * 32 * K_DIM + pkc;
                fb[2 * u]     = *(const float4*)src;
                fb[2 * u + 1] = *(const float4*)(src + 4);
            }
            const uint32_t sB = sbase + pst * STAGE_BYTES + TILE_BYTES;
            #pragma unroll
            for (int u = 0; u < 4; ++u)
                cpa16(sB + aoff0 + u * 4096u,
                      g_B + (size_t)(n0 + r0 + u * 32) * K_DIM + pkc + ch * 8);
        }
        cpa_commit();

        const uint32_t sA = sbase + st * STAGE_BYTES;
        const uint32_t sB = sA + TILE_BYTES;

        #pragma unroll
        for (int ks = 0; ks < 4; ++ks) {
            const int chn = ks * 2 + lc;
            uint32_t a[4][4], b[2][4];
            #pragma unroll
            for (int ms = 0; ms < 4; ++ms) {
                const int row = arow0 + ms * 16;
                ldsm_x4(a[ms], sA + (uint32_t)(row * 8 + (chn ^ (row & 7))) * 16u);
            }
            #pragma unroll
            for (int bs = 0; bs < 2; ++bs) {
                const int row = brow0 + bs * 16;
                ldsm_x4(b[bs], sB + (uint32_t)(row * 8 + (chn ^ (row & 7))) * 16u);
            }
            #pragma unroll
            for (int ms = 0; ms < 4; ++ms)
                #pragma unroll
                for (int nb = 0; nb < 4; ++nb)
                    mma_fp16(acc[ms][nb], a[ms], b[nb >> 1][nb & 1], b[nb >> 1][2 + (nb & 1)]);
        }

        if (pf) {
            // convert + store A for stage it+2 (LDGs long complete by now)
            unsigned char* sAp = dyn_smem + pst * STAGE_BYTES;
            #pragma unroll
            for (int u = 0; u < 4; ++u)
                sts_a8(sAp, aoff0 + u * 4096u, fb[2 * u], fb[2 * u + 1]);
        }
        // no trailing barrier: next iteration's top barrier provides ordering
    }

    // Epilogue: bias add + float2 stores
    const int ln4 = lane & 3;
    const int lg  = lane >> 2;
    float2 bv[4];
    #pragma unroll
    for (int nb = 0; nb < 4; ++nb) {
        const int c = n0 + wn * 32 + nb * 8 + ln4 * 2;
        bv[nb].x = __ldg(bias + c);
        bv[nb].y = __ldg(bias + c + 1);
    }
    #pragma unroll
    for (int ms = 0; ms < 4; ++ms) {
        const int rr = m0 + wm * 64 + ms * 16 + lg;
        #pragma unroll
        for (int nb = 0; nb < 4; ++nb) {
            const int c = n0 + wn * 32 + nb * 8 + ln4 * 2;
            float2 o0, o1;
            o0.x = acc[ms][nb][0] + bv[nb].x;
            o0.y = acc[ms][nb][1] + bv[nb].y;
            o1.x = acc[ms][nb][2] + bv[nb].x;
            o1.y = acc[ms][nb][3] + bv[nb].y;
            *(float2*)(y + (size_t)rr * N_DIM + c)       = o0;
            *(float2*)(y + (size_t)(rr + 8) * N_DIM + c) = o1;
        }
    }
}

// ---------------------------------------------------------------------------
extern "C" void kernel_launch(void* const* d_in, const int* in_sizes, int n_in,
                              void* d_out, int out_size) {
    const float* x    = (const float*)d_in[0];   // [8,2048,2048]
    const float* w    = (const float*)d_in[1];   // [2048,2048]
    const float* bias = (const float*)d_in[2];   // [2048]
    float* y = (float*)d_out;

    const int M = in_sizes[0] / K_DIM;           // 16384

    cudaFuncSetAttribute(gemm_mma, cudaFuncAttributeMaxDynamicSharedMemorySize,
                         STAGES * STAGE_BYTES);

    prep_kernel<<<MASK_BLOCKS, 256>>>(w);

    const int grid = (M / BM) * (N_DIM / BN);    // 128 * 16 = 2048
    gemm_mma<<<grid, 256, STAGES * STAGE_BYTES>>>(x, bias, y);
}

// round 14
// speedup vs baseline: 1.1035x; 1.1035x over previous
#include <cuda_runtime.h>
#include <cuda_fp16.h>
#include <stdint.h>
#include <string.h>

#define K_DIM 2048
#define N_DIM 2048
#define TOPK  1024
#define BM 128
#define BN 128
#define BK 64
#define STAGES 3
#define TILE_BYTES (BM * BK * 2)          // 16 KB per operand tile
#define STAGE_BYTES (2 * TILE_BYTES)      // A + B = 32 KB
#define NITER (K_DIM / BK)                // 32
#define MASK_BLOCKS 2048
#define CONV_BLOCKS 4096                  // (16384*2048/32)/256

// Row-major fp16 scratch (device globals: allocation-free rule)
__device__ __align__(16) __half g_A[(size_t)16384 * K_DIM];
__device__ __align__(16) __half g_B[(size_t)N_DIM * K_DIM];

// ---------------------------------------------------------------------------
// PTX helpers (baseline sm_80+ features only: valid for compute_103 PTX)
// ---------------------------------------------------------------------------
__device__ __forceinline__ uint32_t smem_u32(const void* p) {
    uint32_t a;
    asm("{ .reg .u64 t; cvta.to.shared.u64 t, %1; cvt.u32.u64 %0, t; }" : "=r"(a) : "l"(p));
    return a;
}
__device__ __forceinline__ void cpa16(uint32_t dst, const void* src) {
    asm volatile("cp.async.cg.shared.global [%0], [%1], 16;" :: "r"(dst), "l"(src) : "memory");
}
__device__ __forceinline__ void cpa_commit() {
    asm volatile("cp.async.commit_group;" ::: "memory");
}
__device__ __forceinline__ void cpa_wait1() {
    asm volatile("cp.async.wait_group 1;" ::: "memory");
}
__device__ __forceinline__ void ldsm_x4(uint32_t (&r)[4], uint32_t addr) {
    asm volatile("ldmatrix.sync.aligned.m8n8.x4.shared.b16 {%0,%1,%2,%3}, [%4];"
                 : "=r"(r[0]), "=r"(r[1]), "=r"(r[2]), "=r"(r[3]) : "r"(addr));
}
__device__ __forceinline__ void mma_fp16(float (&c)[4], const uint32_t (&a)[4],
                                         uint32_t b0, uint32_t b1) {
    asm volatile(
        "mma.sync.aligned.m16n8k16.row.col.f32.f16.f16.f32 "
        "{%0,%1,%2,%3}, {%4,%5,%6,%7}, {%8,%9}, {%0,%1,%2,%3};"
        : "+f"(c[0]), "+f"(c[1]), "+f"(c[2]), "+f"(c[3])
        : "r"(a[0]), "r"(a[1]), "r"(a[2]), "r"(a[3]), "r"(b0), "r"(b1));
}
// Streaming (evict-first) float4 load: x is read exactly once.
__device__ __forceinline__ float4 ldg_cs4(const float* p) {
    float4 v;
    asm volatile("ld.global.cs.v4.f32 {%0,%1,%2,%3}, [%4];"
                 : "=f"(v.x), "=f"(v.y), "=f"(v.z), "=f"(v.w) : "l"(p));
    return v;
}
__device__ __forceinline__ uint4 cvt8(const float4& a, const float4& b) {
    __half2 h0 = __floats2half2_rn(a.x, a.y);
    __half2 h1 = __floats2half2_rn(a.z, a.w);
    __half2 h2 = __floats2half2_rn(b.x, b.y);
    __half2 h3 = __floats2half2_rn(b.z, b.w);
    uint4 pk;
    memcpy(&pk.x, &h0, 4); memcpy(&pk.y, &h1, 4);
    memcpy(&pk.z, &h2, 4); memcpy(&pk.w, &h3, 4);
    return pk;
}

// ---------------------------------------------------------------------------
// Fused prep kernel (lightweight on both paths so the memory-bound convert
// path keeps full occupancy):
//   blocks [0, MASK_BLOCKS):   per-row exact top-k radix select -> g_B fp16
//   blocks [MASK_BLOCKS, ...): x fp32 -> fp16 into g_A, 32 floats/thread
// ---------------------------------------------------------------------------
__global__ __launch_bounds__(256) void prep_kernel(const float* __restrict__ w,
                                                   const float* __restrict__ x) {
    __shared__ unsigned int bits[K_DIM];
    __shared__ unsigned int hA[256];
    __shared__ unsigned int hBuf[256];
    __shared__ unsigned int s_prefix, s_kwant, s_cnt_gt, s_cnt_eq;

    const int tid = threadIdx.x;

    if (blockIdx.x >= MASK_BLOCKS) {
        // ---- convert path: 32 floats per thread, 2 independent 16-float groups
        const size_t t = (size_t)(blockIdx.x - MASK_BLOCKS) * 256 + tid;
        const size_t base = t * 32;
        const float* src = x + base;

        float4 v0 = ldg_cs4(src);
        float4 v1 = ldg_cs4(src + 4);
        float4 v2 = ldg_cs4(src + 8);
        float4 v3 = ldg_cs4(src + 12);
        float4 v4 = ldg_cs4(src + 16);
        float4 v5 = ldg_cs4(src + 20);
        float4 v6 = ldg_cs4(src + 24);
        float4 v7 = ldg_cs4(src + 28);

        *(uint4*)(g_A + base)      = cvt8(v0, v1);
        *(uint4*)(g_A + base + 8)  = cvt8(v2, v3);
        *(uint4*)(g_A + base + 16) = cvt8(v4, v5);
        *(uint4*)(g_A + base + 24) = cvt8(v6, v7);
        return;
    }

    // ---- mask path ----
    const int row = blockIdx.x;
    const float* wr = w + (size_t)row * K_DIM;

    for (int i = tid; i < K_DIM; i += 256)
        bits[i] = __float_as_uint(wr[i]) & 0x7FFFFFFFu;
    if (tid == 0) { s_cnt_gt = 0; s_cnt_eq = 0; }
    __syncthreads();

    unsigned int prefix = 0, kwant = TOPK;
    #pragma unroll
    for (int pass = 3; pass >= 0; --pass) {
        const int shift = pass * 8;
        hA[tid] = 0;
        __syncthreads();
        if (pass == 3) {
            for (int i = tid; i < K_DIM; i += 256)
                atomicAdd(&hA[(bits[i] >> shift) & 0xFFu], 1u);
        } else {
            const unsigned int hi_mask = 0xFFFFFFFFu << (shift + 8);
            for (int i = tid; i < K_DIM; i += 256) {
                const unsigned int b = bits[i];
                if ((b & hi_mask) == (prefix & hi_mask))
                    atomicAdd(&hA[(b >> shift) & 0xFFu], 1u);
            }
        }
        __syncthreads();

        // Parallel inclusive suffix scan: S(i) = sum_{j>=i} hist[j]
        unsigned int* cur = hA;
        unsigned int* nxt = hBuf;
        unsigned int v = cur[tid];
        #pragma unroll
        for (int step = 1; step < 256; step <<= 1) {
            unsigned int add = (tid + step < 256) ? cur[tid + step] : 0u;
            v += add;
            nxt[tid] = v;
            unsigned int* tmp = cur; cur = nxt; nxt = tmp;
            __syncthreads();
        }
        const unsigned int S_next = (tid == 255) ? 0u : cur[tid + 1];
        if (v >= kwant && S_next < kwant) {
            s_prefix = prefix | ((unsigned int)tid << shift);
            s_kwant  = kwant - S_next;
        }
        __syncthreads();
        prefix = s_prefix;
        kwant  = s_kwant;
        __syncthreads();
    }
    const unsigned int thresh = prefix;

    unsigned int local_gt = 0, local_eq = 0;
    for (int i = tid; i < K_DIM; i += 256) {
        local_gt += (bits[i] > thresh);
        local_eq += (bits[i] == thresh);
    }
    if (local_gt) atomicAdd(&s_cnt_gt, local_gt);
    if (local_eq) atomicAdd(&s_cnt_eq, local_eq);
    __syncthreads();
    const unsigned int need_eq = TOPK - s_cnt_gt;
    const bool keep_all_eq = (s_cnt_eq == need_eq);   // no true fp ties (common)

    for (int i = tid; i < K_DIM; i += 256) {
        const unsigned int b = bits[i];
        float val = 0.0f;
        if (b > thresh) {
            val = wr[i];
        } else if (b == thresh) {
            if (keep_all_eq) {
                val = wr[i];
            } else {
                unsigned int rr = 0;
                for (int j = 0; j < i; ++j) rr += (bits[j] == thresh);
                if (rr < need_eq) val = wr[i];
            }
        }
        g_B[(size_t)row * K_DIM + i] = __float2half_rn(val);
    }
}

// ---------------------------------------------------------------------------
// GEMM: pipelined mma.sync fp16, K = 2048 (round-12 configuration, best).
// 128x128 tile/CTA, 256 thr (2x4 warps of 64x32), 3-stage cp.async pipeline,
// SINGLE barrier per K-iteration.
// ---------------------------------------------------------------------------
__device__ __forceinline__ void load_stage(uint32_t sbase, int st, int kc,
                                           int m0, int n0, int tid) {
    const uint32_t sA = sbase + st * STAGE_BYTES;
    const uint32_t sB = sA + TILE_BYTES;
    #pragma unroll
    for (int u = 0; u < 4; ++u) {
        const int f   = tid + u * 256;
        const int row = f >> 3;
        const int ch  = f & 7;
        const uint32_t so = (uint32_t)(row * 8 + (ch ^ (row & 7))) * 16u;
        cpa16(sA + so, g_A + (size_t)(m0 + row) * K_DIM + kc + ch * 8);
        cpa16(sB + so, g_B + (size_t)(n0 + row) * K_DIM + kc + ch * 8);
    }
}

__global__ void __launch_bounds__(256, 2) gemm_mma(const float* __restrict__ bias,
                                                   float* __restrict__ y) {
    extern __shared__ unsigned char dyn_smem[];
    const uint32_t sbase = smem_u32(dyn_smem);

    const int tid  = threadIdx.x;
    const int wid  = tid >> 5;
    const int lane = tid & 31;
    const int m_tile = blockIdx.x >> 4;
    const int n_tile = blockIdx.x & 15;
    const int m0 = m_tile * BM;
    const int n0 = n_tile * BN;

    const int wm = wid >> 2;          // 0..1
    const int wn = wid & 3;           // 0..3
    const int lr = lane & 15;         // ldmatrix row within 16
    const int lc = lane >> 4;         // ldmatrix k-chunk selector
    const int arow0 = wm * 64 + lr;
    const int brow0 = wn * 32 + lr;

    float acc[4][4][4];
    #pragma unroll
    for (int i = 0; i < 4; ++i)
        #pragma unroll
        for (int j = 0; j < 4; ++j)
            #pragma unroll
            for (int r = 0; r < 4; ++r) acc[i][j][r] = 0.0f;

    load_stage(sbase, 0, 0, m0, n0, tid); cpa_commit();
    load_stage(sbase, 1, BK, m0, n0, tid); cpa_commit();

    for (int it = 0; it < NITER; ++it) {
        const int st = it % STAGES;
        cpa_wait1();          // stage `it` landed (1 newer group pending)
        __syncthreads();      // loads visible; compute of it-1 finished, so
                              // stage (it+2)%3 == (it-1)%3 is free to overwrite

        if (it + 2 < NITER) load_stage(sbase, (it + 2) % STAGES, (it + 2) * BK, m0, n0, tid);
        cpa_commit();

        const uint32_t sA = sbase + st * STAGE_BYTES;
        const uint32_t sB = sA + TILE_BYTES;

        #pragma unroll
        for (int ks = 0; ks < 4; ++ks) {
            const int ch = ks * 2 + lc;
            uint32_t a[4][4], b[2][4];
            #pragma unroll
            for (int ms = 0; ms < 4; ++ms) {
                const int row = arow0 + ms * 16;
                ldsm_x4(a[ms], sA + (uint32_t)(row * 8 + (ch ^ (row & 7))) * 16u);
            }
            #pragma unroll
            for (int bs = 0; bs < 2; ++bs) {
                const int row = brow0 + bs * 16;
                ldsm_x4(b[bs], sB + (uint32_t)(row * 8 + (ch ^ (row & 7))) * 16u);
            }
            #pragma unroll
            for (int ms = 0; ms < 4; ++ms)
                #pragma unroll
                for (int nb = 0; nb < 4; ++nb)
                    mma_fp16(acc[ms][nb], a[ms], b[nb >> 1][nb & 1], b[nb >> 1][2 + (nb & 1)]);
        }
        // no trailing barrier: next iteration's top barrier provides ordering
    }

    // Epilogue: bias add + float2 stores
    const int ln4 = lane & 3;
    const int lg  = lane >> 2;
    float2 bv[4];
    #pragma unroll
    for (int nb = 0; nb < 4; ++nb) {
        const int c = n0 + wn * 32 + nb * 8 + ln4 * 2;
        bv[nb].x = __ldg(bias + c);
        bv[nb].y = __ldg(bias + c + 1);
    }
    #pragma unroll
    for (int ms = 0; ms < 4; ++ms) {
        const int r0 = m0 + wm * 64 + ms * 16 + lg;
        #pragma unroll
        for (int nb = 0; nb < 4; ++nb) {
            const int c = n0 + wn * 32 + nb * 8 + ln4 * 2;
            float2 o0, o1;
            o0.x = acc[ms][nb][0] + bv[nb].x;
            o0.y = acc[ms][nb][1] + bv[nb].y;
            o1.x = acc[ms][nb][2] + bv[nb].x;
            o1.y = acc[ms][nb][3] + bv[nb].y;
            *(float2*)(y + (size_t)r0 * N_DIM + c)       = o0;
            *(float2*)(y + (size_t)(r0 + 8) * N_DIM + c) = o1;
        }
    }
}

// ---------------------------------------------------------------------------
extern "C" void kernel_launch(void* const* d_in, const int* in_sizes, int n_in,
                              void* d_out, int out_size) {
    const float* x    = (const float*)d_in[0];   // [8,2048,2048]
    const float* w    = (const float*)d_in[1];   // [2048,2048]
    const float* bias = (const float*)d_in[2];   // [2048]
    float* y = (float*)d_out;

    const int M = in_sizes[0] / K_DIM;           // 16384

    cudaFuncSetAttribute(gemm_mma, cudaFuncAttributeMaxDynamicSharedMemorySize,
                         STAGES * STAGE_BYTES);

    prep_kernel<<<MASK_BLOCKS + CONV_BLOCKS, 256>>>(w, x);

    const int grid = (M / BM) * (N_DIM / BN);    // 128 * 16 = 2048
    gemm_mma<<<grid, 256, STAGES * STAGE_BYTES>>>(bias, y);
}